// round 2
// baseline (speedup 1.0000x reference)
#include <cuda_runtime.h>

#define B_    64
#define T_    512
#define D_    768
#define H_    384
#define G4H   1536
#define N2    3072
#define MTOT  32768
#define KTAGS 16
#define START_TAG 14
#define NEGV  (-10000.0f)

// ---- static device scratch (allocation-free) ----
__device__ float g_xg[(size_t)MTOT * N2];     // gate pre-acts, reused per layer
__device__ float g_l1[(size_t)MTOT * D_];     // layer-1 output
__device__ float g_l2[(size_t)MTOT * D_];     // layer-2 output
__device__ float g_feats[(size_t)MTOT * KTAGS];
__device__ float g_h[2 * 2 * H_ * B_];        // [buf][dir][u][b] h double-buffer
__device__ unsigned int g_bc, g_bg;           // grid barrier

// ---- accurate activations (immune to fast-math flags) ----
__device__ __forceinline__ float exp_acc(float x) {
    x = fminf(fmaxf(x, -80.f), 80.f);
    float n = rintf(x * 1.4426950408889634f);
    float r = fmaf(n, -0.693145751953125f, x);
    r = fmaf(n, -1.4286068203e-06f, r);
    float p = 1.9841269841e-4f;
    p = fmaf(p, r, 1.3888888889e-3f); p = fmaf(p, r, 8.3333333333e-3f);
    p = fmaf(p, r, 4.1666666667e-2f); p = fmaf(p, r, 1.6666666667e-1f);
    p = fmaf(p, r, 0.5f); p = fmaf(p, r, 1.0f); p = fmaf(p, r, 1.0f);
    return p * __int_as_float(((int)n + 127) << 23);
}
__device__ __forceinline__ float sig_acc(float x) { return 1.f / (1.f + exp_acc(-x)); }
__device__ __forceinline__ float tanh_acc(float x) {
    float e = exp_acc(-2.f * fabsf(x));
    float t = 1.f - 2.f * e / (1.f + e);
    return (x < 0.f) ? -t : t;
}

__device__ __forceinline__ void grid_barrier(int nb) {
    __threadfence(); __syncthreads();
    if (threadIdx.x == 0) {
        unsigned int gen = *(volatile unsigned int*)&g_bg;
        if (atomicAdd(&g_bc, 1u) == (unsigned)nb - 1) {
            g_bc = 0u; __threadfence(); atomicAdd(&g_bg, 1u);
        } else {
            while (*(volatile unsigned int*)&g_bg == gen) __nanosleep(64);
        }
    }
    __syncthreads();
}

// ============ SGEMM: g_xg[M=32768][N=3072] = A[M][768]*W[N][768]^T + b1+b2 ====
__global__ __launch_bounds__(256) void sgemm_xg(
    const float* __restrict__ Aext, const float* __restrict__ W,
    const float* __restrict__ b1, const float* __restrict__ b2, int layer)
{
    const float* A = layer ? (const float*)g_l1 : Aext;
    __shared__ float sA[16][128], sB[16][128];
    const int tid = threadIdx.x, tn = tid & 15, tm = tid >> 4;
    const int m0 = blockIdx.y * 128, n0 = blockIdx.x * 128;
    float acc[8][8];
#pragma unroll
    for (int i = 0; i < 8; i++)
#pragma unroll
        for (int j = 0; j < 8; j++) acc[i][j] = 0.f;

    for (int kt = 0; kt < D_; kt += 16) {
#pragma unroll
        for (int l = 0; l < 2; l++) {
            int idx = tid * 2 + l, r = idx >> 2, c4 = idx & 3;
            float4 va = *(const float4*)(A + (size_t)(m0 + r) * D_ + kt + c4 * 4);
            sA[c4*4+0][r]=va.x; sA[c4*4+1][r]=va.y; sA[c4*4+2][r]=va.z; sA[c4*4+3][r]=va.w;
            float4 vb = *(const float4*)(W + (size_t)(n0 + r) * D_ + kt + c4 * 4);
            sB[c4*4+0][r]=vb.x; sB[c4*4+1][r]=vb.y; sB[c4*4+2][r]=vb.z; sB[c4*4+3][r]=vb.w;
        }
        __syncthreads();
#pragma unroll
        for (int k = 0; k < 16; k++) {
            float a[8], bb[8];
            *(float4*)(a)   = *(const float4*)(&sA[k][tm*8]);
            *(float4*)(a+4) = *(const float4*)(&sA[k][tm*8+4]);
            *(float4*)(bb)  = *(const float4*)(&sB[k][tn*8]);
            *(float4*)(bb+4)= *(const float4*)(&sB[k][tn*8+4]);
#pragma unroll
            for (int i = 0; i < 8; i++)
#pragma unroll
                for (int j = 0; j < 8; j++) acc[i][j] = fmaf(a[i], bb[j], acc[i][j]);
        }
        __syncthreads();
    }
    float bs[8];
#pragma unroll
    for (int j = 0; j < 8; j++) { int n = n0 + tn*8 + j; bs[j] = b1[n] + b2[n]; }
#pragma unroll
    for (int i = 0; i < 8; i++) {
        float* cp = g_xg + (size_t)(m0 + tm*8 + i) * N2 + n0 + tn*8;
#pragma unroll
        for (int j = 0; j < 8; j++) cp[j] = acc[i][j] + bs[j];
    }
}

// ============ persistent recurrence: 128 CTAs, 192 thr, 1/SM ================
#define REC_SMEMB ((9216 + 24576) * 4)
__global__ __launch_bounds__(192, 1) void lstm_rec(
    const float* __restrict__ w_hh, int layer)
{
    extern __shared__ float sm[];
    float* sW = sm;          // [24][384]
    float* sH = sm + 9216;   // [384][64]
    float* h_out = layer ? g_l2 : g_l1;
    const int tid = threadIdx.x, bid = blockIdx.x;
    const int d = bid >> 6, u0 = (bid & 63) * 6;
    const int ul = tid / 32, bg = tid & 31, b0 = 2*bg, b1 = b0 + 1;

    {   // stationary W_hh slice
        const float* Wb = w_hh + (size_t)(layer*2 + d) * G4H * H_;
#pragma unroll
        for (int g = 0; g < 4; g++) {
            const float4* src = (const float4*)(Wb + (size_t)(g*H_ + u0 + ul) * H_);
            float4* dst = (float4*)(sW + (ul*4 + g) * H_);
            for (int q = bg; q < 96; q += 32) dst[q] = src[q];
        }
    }
    float c0 = 0.f, c1 = 0.f;
    const int col = d * G4H + u0 + ul;

    for (int s = 0; s < T_; s++) {
        const int t = d ? (T_ - 1 - s) : s;
        float acc[4][2];
        {
            const float* x0 = g_xg + (size_t)(b0*T_ + t) * N2 + col;
            const float* x1 = g_xg + (size_t)(b1*T_ + t) * N2 + col;
#pragma unroll
            for (int g = 0; g < 4; g++) { acc[g][0] = x0[g*H_]; acc[g][1] = x1[g*H_]; }
        }
        if (s == 0) {
            float4 z = make_float4(0.f,0.f,0.f,0.f);
            for (int i = tid; i < 6144; i += 192) ((float4*)sH)[i] = z;
        } else {
            const float4* src = (const float4*)(g_h + (size_t)(((s-1)&1)*2 + d) * H_ * B_);
            float4* dsh = (float4*)sH;
            for (int i = tid; i < 6144; i += 192) dsh[i] = src[i];
        }
        __syncthreads();
        {
            const float* wp = sW + (ul*4) * H_;
#pragma unroll 4
            for (int k = 0; k < H_; k += 2) {
                float2 w0 = *(const float2*)(wp + k);
                float2 w1 = *(const float2*)(wp + H_ + k);
                float2 w2 = *(const float2*)(wp + 2*H_ + k);
                float2 w3 = *(const float2*)(wp + 3*H_ + k);
                float2 ha = *(const float2*)(sH + k*B_ + b0);
                float2 hb = *(const float2*)(sH + (k+1)*B_ + b0);
                acc[0][0]=fmaf(w0.x,ha.x,acc[0][0]); acc[0][1]=fmaf(w0.x,ha.y,acc[0][1]);
                acc[1][0]=fmaf(w1.x,ha.x,acc[1][0]); acc[1][1]=fmaf(w1.x,ha.y,acc[1][1]);
                acc[2][0]=fmaf(w2.x,ha.x,acc[2][0]); acc[2][1]=fmaf(w2.x,ha.y,acc[2][1]);
                acc[3][0]=fmaf(w3.x,ha.x,acc[3][0]); acc[3][1]=fmaf(w3.x,ha.y,acc[3][1]);
                acc[0][0]=fmaf(w0.y,hb.x,acc[0][0]); acc[0][1]=fmaf(w0.y,hb.y,acc[0][1]);
                acc[1][0]=fmaf(w1.y,hb.x,acc[1][0]); acc[1][1]=fmaf(w1.y,hb.y,acc[1][1]);
                acc[2][0]=fmaf(w2.y,hb.x,acc[2][0]); acc[2][1]=fmaf(w2.y,hb.y,acc[2][1]);
                acc[3][0]=fmaf(w3.y,hb.x,acc[3][0]); acc[3][1]=fmaf(w3.y,hb.y,acc[3][1]);
            }
        }
        float i0=sig_acc(acc[0][0]), f0=sig_acc(acc[1][0]), gg0=tanh_acc(acc[2][0]), o0=sig_acc(acc[3][0]);
        c0 = f0*c0 + i0*gg0; float hv0 = o0 * tanh_acc(c0);
        float i1=sig_acc(acc[0][1]), f1=sig_acc(acc[1][1]), gg1=tanh_acc(acc[2][1]), o1=sig_acc(acc[3][1]);
        c1 = f1*c1 + i1*gg1; float hv1 = o1 * tanh_acc(c1);

        float* hw = g_h + ((size_t)((s&1)*2 + d) * H_ + u0 + ul) * B_;
        hw[b0] = hv0; hw[b1] = hv1;
        h_out[(size_t)(b0*T_ + t) * D_ + d*H_ + u0 + ul] = hv0;
        h_out[(size_t)(b1*T_ + t) * D_ + d*H_ + u0 + ul] = hv1;
        grid_barrier(gridDim.x);
    }
}

// ============ projection ====================================================
__global__ __launch_bounds__(256) void proj_kernel(
    const float* __restrict__ wout, const float* __restrict__ bout)
{
    __shared__ float sX[16 * D_];
    const int tid = threadIdx.x, row0 = blockIdx.x * 16;
    const float4* src = (const float4*)(g_l2 + (size_t)row0 * D_);
    for (int i = tid; i < 16 * D_ / 4; i += 256) ((float4*)sX)[i] = src[i];
    __syncthreads();
    const int r = tid >> 4, k = tid & 15;
    const float4* xr = (const float4*)(sX + r * D_);
    const float4* wr = (const float4*)(wout + (size_t)k * D_);
    float acc = 0.f;
#pragma unroll 8
    for (int i = 0; i < D_ / 4; i++) {
        float4 a = xr[i], w = wr[i];
        acc = fmaf(a.x, w.x, acc); acc = fmaf(a.y, w.y, acc);
        acc = fmaf(a.z, w.z, acc); acc = fmaf(a.w, w.w, acc);
    }
    g_feats[(size_t)(row0 + r) * KTAGS + k] = acc + bout[k];
}

// ============ Viterbi (exact first-max argmax) ==============================
__global__ __launch_bounds__(32) void viterbi_kernel(
    const float* __restrict__ trans, float* __restrict__ out, int out_size)
{
    __shared__ float sT[KTAGS*KTAGS], sD[KTAGS], sDn[KTAGS];
    __shared__ unsigned char psi[T_-1][KTAGS];
    const int b = blockIdx.x, tid = threadIdx.x;
    for (int i = tid; i < KTAGS*KTAGS; i += 32) sT[i] = trans[i];
    if (tid < KTAGS) sD[tid] = (tid == START_TAG) ? 0.f : NEGV;
    __syncthreads();
    const float* fb = g_feats + (size_t)b * T_ * KTAGS;
    for (int t = 1; t < T_; t++) {
        if (tid < KTAGS) {
            float best = -3.0e38f; int bi = 0;
#pragma unroll
            for (int j = 0; j < KTAGS; j++) {
                float v = sD[j] + sT[tid*KTAGS + j];
                if (v > best) { best = v; bi = j; }
            }
            psi[t-1][tid] = (unsigned char)bi;
            sDn[tid] = best + fb[t*KTAGS + tid];
        }
        __syncthreads();
        if (tid < KTAGS) sD[tid] = sDn[tid];
        __syncthreads();
    }
    if (tid == 0) {
        float best = -3.0e38f; int last = 0;
        for (int k = 0; k < KTAGS; k++) if (sD[k] > best) { best = sD[k]; last = k; }
        float* so = nullptr; float* po = nullptr;
        if (out_size >= B_ + B_*T_) { so = out; po = out + B_; }
        else if (out_size >= B_*T_) { po = out; }
        else { so = out; }
        if (so) so[b] = best;
        if (po) {
            po[(size_t)b*T_ + T_-1] = (float)last;
            int cur = last;
            for (int t = T_-2; t >= 0; t--) { cur = psi[t][cur]; po[(size_t)b*T_ + t] = (float)cur; }
        }
    }
}

// ============ launcher ======================================================
extern "C" void kernel_launch(void* const* d_in, const int* in_sizes, int n_in,
                              void* d_out, int out_size)
{
    const float* encoded = (const float*)d_in[0];
    const float* w_ih    = (const float*)d_in[1];
    const float* w_hh    = (const float*)d_in[2];
    const float* b_ih    = (const float*)d_in[3];
    const float* b_hh    = (const float*)d_in[4];
    const float* w_out   = (const float*)d_in[5];
    const float* b_out   = (const float*)d_in[6];
    const float* trans   = (const float*)d_in[7];

    cudaFuncSetAttribute(lstm_rec, cudaFuncAttributeMaxDynamicSharedMemorySize, REC_SMEMB);

    dim3 gg(N2 / 128, MTOT / 128);
    for (int layer = 0; layer < 2; layer++) {
        const float* W  = w_ih + (size_t)layer * 2 * G4H * D_;
        const float* bi = b_ih + (size_t)layer * 2 * G4H;
        const float* bh = b_hh + (size_t)layer * 2 * G4H;
        sgemm_xg<<<gg, 256>>>(encoded, W, bi, bh, layer);
        lstm_rec<<<128, 192, REC_SMEMB>>>(w_hh, layer);
    }
    proj_kernel<<<MTOT / 16, 256>>>(w_out, b_out);
    viterbi_kernel<<<B_, 32>>>(trans, (float*)d_out, out_size);
}

// round 5
// speedup vs baseline: 1.0757x; 1.0757x over previous
#include <cuda_runtime.h>
#include <cstdint>

#define B_    64
#define T_    512
#define D_    768
#define H_    384
#define G4H   1536
#define N2    3072
#define MTOT  32768
#define KTAGS 16
#define START_TAG 14
#define NEGV  (-10000.0f)

// ---- static device scratch ----
__device__ float g_xg[(size_t)MTOT * N2];
__device__ float g_l1[(size_t)MTOT * D_];
__device__ float g_l2[(size_t)MTOT * D_];
__device__ float g_feats[(size_t)MTOT * KTAGS];
__device__ float g_h[2 * 2 * H_ * B_];
__device__ unsigned int g_bcd[2], g_bgd[2];

// ---- accurate activations ----
__device__ __forceinline__ float exp_acc(float x) {
    x = fminf(fmaxf(x, -80.f), 80.f);
    float n = rintf(x * 1.4426950408889634f);
    float r = fmaf(n, -0.693145751953125f, x);
    r = fmaf(n, -1.4286068203e-06f, r);
    float p = 1.9841269841e-4f;
    p = fmaf(p, r, 1.3888888889e-3f); p = fmaf(p, r, 8.3333333333e-3f);
    p = fmaf(p, r, 4.1666666667e-2f); p = fmaf(p, r, 1.6666666667e-1f);
    p = fmaf(p, r, 0.5f); p = fmaf(p, r, 1.0f); p = fmaf(p, r, 1.0f);
    return p * __int_as_float(((int)n + 127) << 23);
}
__device__ __forceinline__ float sig_acc(float x) { return 1.f / (1.f + exp_acc(-x)); }
__device__ __forceinline__ float tanh_acc(float x) {
    float e = exp_acc(-2.f * fabsf(x));
    float t = 1.f - 2.f * e / (1.f + e);
    return (x < 0.f) ? -t : t;
}

// ================= tf32x3 mma.sync GEMM =================
// g_xg[M=32768][N=3072] = A[M][768]*W[N][768]^T + b1 + b2
// cvt.rna.tf32.f32 needs a .b32 destination => "=r".
__device__ __forceinline__ unsigned cvt_tf32(float x) {
    unsigned u;
    asm("cvt.rna.tf32.f32 %0, %1;" : "=r"(u) : "f"(x));
    return u;
}
__device__ __forceinline__ void tf32_split_u(float x, unsigned& hi, unsigned& lo) {
    hi = cvt_tf32(x);
    float d = x - __uint_as_float(hi);
    lo = cvt_tf32(d);
}
#define MMA_T(C, a0, a1, a2, a3, bb0, bb1) \
    asm volatile("mma.sync.aligned.m16n8k8.row.col.f32.tf32.tf32.f32 " \
        "{%0,%1,%2,%3},{%4,%5,%6,%7},{%8,%9},{%0,%1,%2,%3};" \
        : "+f"(C[0]), "+f"(C[1]), "+f"(C[2]), "+f"(C[3]) \
        : "r"(a0), "r"(a1), "r"(a2), "r"(a3), "r"(bb0), "r"(bb1))

__global__ __launch_bounds__(256) void gemm_tf32(
    const float* __restrict__ Aext, const float* __restrict__ W,
    const float* __restrict__ b1, const float* __restrict__ b2, int layer)
{
    const float* A = layer ? (const float*)g_l1 : Aext;
    __shared__ float sA[128 * 36], sB[128 * 36];
    const int tid = threadIdx.x, wid = tid >> 5, lane = tid & 31;
    const int m0 = blockIdx.y * 128, n0 = blockIdx.x * 128;
    const int r = tid >> 1, c0 = (tid & 1) * 16;
    const int wm = (wid >> 2) * 64, wn = (wid & 3) * 32;
    const int r4 = lane >> 2, c4 = lane & 3;

    const float* ap = A + (size_t)(m0 + r) * D_ + c0;
    const float* wp = W + (size_t)(n0 + r) * D_ + c0;
    float4 aR[4], wR[4];
#pragma unroll
    for (int j = 0; j < 4; j++) { aR[j] = *(const float4*)(ap + 4 * j); wR[j] = *(const float4*)(wp + 4 * j); }

    float acc[4][4][4];
#pragma unroll
    for (int i = 0; i < 4; i++)
#pragma unroll
        for (int j = 0; j < 4; j++)
#pragma unroll
            for (int q = 0; q < 4; q++) acc[i][j][q] = 0.f;

    for (int kt = 0; kt < 24; kt++) {
#pragma unroll
        for (int j = 0; j < 4; j++) {
            *(float4*)(sA + r * 36 + c0 + 4 * j) = aR[j];
            *(float4*)(sB + r * 36 + c0 + 4 * j) = wR[j];
        }
        __syncthreads();
        if (kt < 23) {
            int ko = (kt + 1) * 32;
#pragma unroll
            for (int j = 0; j < 4; j++) {
                aR[j] = *(const float4*)(ap + ko + 4 * j);
                wR[j] = *(const float4*)(wp + ko + 4 * j);
            }
        }
#pragma unroll
        for (int kk = 0; kk < 32; kk += 8) {
            unsigned ah[4][4], al[4][4];
#pragma unroll
            for (int mf = 0; mf < 4; mf++) {
                const float* bp = sA + (wm + mf * 16 + r4) * 36 + kk + c4;
                tf32_split_u(bp[0],          ah[mf][0], al[mf][0]);
                tf32_split_u(bp[8 * 36],     ah[mf][1], al[mf][1]);
                tf32_split_u(bp[4],          ah[mf][2], al[mf][2]);
                tf32_split_u(bp[8 * 36 + 4], ah[mf][3], al[mf][3]);
            }
#pragma unroll
            for (int nf = 0; nf < 4; nf++) {
                const float* bp = sB + (wn + nf * 8 + r4) * 36 + kk + c4;
                unsigned bh0, bl0, bh1, bl1;
                tf32_split_u(bp[0], bh0, bl0);
                tf32_split_u(bp[4], bh1, bl1);
#pragma unroll
                for (int mf = 0; mf < 4; mf++) {
                    MMA_T(acc[mf][nf], ah[mf][0], ah[mf][1], ah[mf][2], ah[mf][3], bh0, bh1);
                    MMA_T(acc[mf][nf], ah[mf][0], ah[mf][1], ah[mf][2], ah[mf][3], bl0, bl1);
                    MMA_T(acc[mf][nf], al[mf][0], al[mf][1], al[mf][2], al[mf][3], bh0, bh1);
                }
            }
        }
        __syncthreads();
    }
#pragma unroll
    for (int nf = 0; nf < 4; nf++) {
        int nb = n0 + wn + nf * 8 + 2 * c4;
        float bs0 = b1[nb] + b2[nb], bs1 = b1[nb + 1] + b2[nb + 1];
#pragma unroll
        for (int mf = 0; mf < 4; mf++) {
            int row = m0 + wm + mf * 16 + r4;
            float2 v0 = make_float2(acc[mf][nf][0] + bs0, acc[mf][nf][1] + bs1);
            float2 v1 = make_float2(acc[mf][nf][2] + bs0, acc[mf][nf][3] + bs1);
            *(float2*)(g_xg + (size_t)row * N2 + nb) = v0;
            *(float2*)(g_xg + (size_t)(row + 8) * N2 + nb) = v1;
        }
    }
}

// ================= persistent recurrence =================
#define REC_SMEMB ((9216 + 24576) * 4)
__device__ __forceinline__ void dir_barrier(int d) {
    __threadfence(); __syncthreads();
    if (threadIdx.x == 0) {
        unsigned gen = *(volatile unsigned*)&g_bgd[d];
        if (atomicAdd(&g_bcd[d], 1u) == 63u) {
            g_bcd[d] = 0u; __threadfence(); atomicAdd(&g_bgd[d], 1u);
        } else {
            while (*(volatile unsigned*)&g_bgd[d] == gen) __nanosleep(32);
        }
    }
    __syncthreads();
}

__global__ __launch_bounds__(192, 1) void lstm_rec(
    const float* __restrict__ w_hh, int layer)
{
    extern __shared__ float sm[];
    float* sW = sm;          // interleaved [u][k2][8]
    float* sH = sm + 9216;   // [384][64]
    float* h_out = layer ? g_l2 : g_l1;
    const int tid = threadIdx.x, bid = blockIdx.x;
    const int d = bid >> 6, u0 = (bid & 63) * 6;
    const int ul = tid / 32, bg = tid & 31, b0 = 2 * bg, b1i = b0 + 1;

    {
        const float* Wb = w_hh + (size_t)(layer * 2 + d) * G4H * H_;
        for (int k = bg; k < H_; k += 32) {
            float* dst = sW + ul * 1536 + (k >> 1) * 8 + (k & 1) * 4;
#pragma unroll
            for (int g = 0; g < 4; g++)
                dst[g] = Wb[(size_t)(g * H_ + u0 + ul) * H_ + k];
        }
    }
    float c0 = 0.f, c1 = 0.f;
    const int col = d * G4H + u0 + ul;

    float xn[4][2];
    {
        int t0 = d ? (T_ - 1) : 0;
        const float* x0 = g_xg + (size_t)(b0 * T_ + t0) * N2 + col;
        const float* x1 = g_xg + (size_t)(b1i * T_ + t0) * N2 + col;
#pragma unroll
        for (int g = 0; g < 4; g++) { xn[g][0] = x0[g * H_]; xn[g][1] = x1[g * H_]; }
    }
    {
        float4 z = make_float4(0.f, 0.f, 0.f, 0.f);
        for (int i = tid; i < 6144; i += 192) ((float4*)sH)[i] = z;
    }

    for (int s = 0; s < T_; s++) {
        const int t = d ? (T_ - 1 - s) : s;
        float acc[4][2];
#pragma unroll
        for (int g = 0; g < 4; g++) { acc[g][0] = xn[g][0]; acc[g][1] = xn[g][1]; }

        if (s > 0) {
            const float4* src = (const float4*)(g_h + (size_t)(((s - 1) & 1) * 2 + d) * H_ * B_);
            float4* dsh = (float4*)sH;
            for (int i = tid; i < 6144; i += 192) dsh[i] = src[i];
        }
        __syncthreads();
        {
            const float* wpt = sW + ul * 1536;
#pragma unroll 4
            for (int k2 = 0; k2 < 192; k2++) {
                float4 w0 = *(const float4*)(wpt + k2 * 8);
                float4 w1 = *(const float4*)(wpt + k2 * 8 + 4);
                float2 ha = *(const float2*)(sH + (2 * k2) * B_ + b0);
                float2 hb = *(const float2*)(sH + (2 * k2 + 1) * B_ + b0);
                acc[0][0] = fmaf(w0.x, ha.x, acc[0][0]); acc[0][1] = fmaf(w0.x, ha.y, acc[0][1]);
                acc[1][0] = fmaf(w0.y, ha.x, acc[1][0]); acc[1][1] = fmaf(w0.y, ha.y, acc[1][1]);
                acc[2][0] = fmaf(w0.z, ha.x, acc[2][0]); acc[2][1] = fmaf(w0.z, ha.y, acc[2][1]);
                acc[3][0] = fmaf(w0.w, ha.x, acc[3][0]); acc[3][1] = fmaf(w0.w, ha.y, acc[3][1]);
                acc[0][0] = fmaf(w1.x, hb.x, acc[0][0]); acc[0][1] = fmaf(w1.x, hb.y, acc[0][1]);
                acc[1][0] = fmaf(w1.y, hb.x, acc[1][0]); acc[1][1] = fmaf(w1.y, hb.y, acc[1][1]);
                acc[2][0] = fmaf(w1.z, hb.x, acc[2][0]); acc[2][1] = fmaf(w1.z, hb.y, acc[2][1]);
                acc[3][0] = fmaf(w1.w, hb.x, acc[3][0]); acc[3][1] = fmaf(w1.w, hb.y, acc[3][1]);
            }
        }
        float i0 = sig_acc(acc[0][0]), f0 = sig_acc(acc[1][0]), gg0 = tanh_acc(acc[2][0]), o0 = sig_acc(acc[3][0]);
        c0 = f0 * c0 + i0 * gg0; float hv0 = o0 * tanh_acc(c0);
        float i1 = sig_acc(acc[0][1]), f1 = sig_acc(acc[1][1]), gg1 = tanh_acc(acc[2][1]), o1 = sig_acc(acc[3][1]);
        c1 = f1 * c1 + i1 * gg1; float hv1 = o1 * tanh_acc(c1);

        float* hw = g_h + ((size_t)((s & 1) * 2 + d) * H_ + u0 + ul) * B_;
        hw[b0] = hv0; hw[b1i] = hv1;
        h_out[(size_t)(b0 * T_ + t) * D_ + d * H_ + u0 + ul] = hv0;
        h_out[(size_t)(b1i * T_ + t) * D_ + d * H_ + u0 + ul] = hv1;

        if (s + 1 < T_) {
            int tn = d ? (T_ - 2 - s) : (s + 1);
            const float* x0 = g_xg + (size_t)(b0 * T_ + tn) * N2 + col;
            const float* x1 = g_xg + (size_t)(b1i * T_ + tn) * N2 + col;
#pragma unroll
            for (int g = 0; g < 4; g++) { xn[g][0] = x0[g * H_]; xn[g][1] = x1[g * H_]; }
        }
        dir_barrier(d);
    }
}

// ================= projection =================
__global__ __launch_bounds__(256) void proj_kernel(
    const float* __restrict__ wout, const float* __restrict__ bout)
{
    __shared__ float sX[16 * D_];
    const int tid = threadIdx.x, row0 = blockIdx.x * 16;
    const float4* src = (const float4*)(g_l2 + (size_t)row0 * D_);
    for (int i = tid; i < 16 * D_ / 4; i += 256) ((float4*)sX)[i] = src[i];
    __syncthreads();
    const int rr = tid >> 4, k = tid & 15;
    const float4* xr = (const float4*)(sX + rr * D_);
    const float4* wr = (const float4*)(wout + (size_t)k * D_);
    float acc = 0.f;
#pragma unroll 8
    for (int i = 0; i < D_ / 4; i++) {
        float4 a = xr[i], w = wr[i];
        acc = fmaf(a.x, w.x, acc); acc = fmaf(a.y, w.y, acc);
        acc = fmaf(a.z, w.z, acc); acc = fmaf(a.w, w.w, acc);
    }
    g_feats[(size_t)(row0 + rr) * KTAGS + k] = acc + bout[k];
}

// ================= Viterbi =================
__global__ __launch_bounds__(32) void viterbi_kernel(
    const float* __restrict__ trans, float* __restrict__ out, int out_size)
{
    __shared__ float sT[KTAGS * KTAGS], sD[KTAGS], sDn[KTAGS];
    __shared__ unsigned char psi[T_ - 1][KTAGS];
    const int b = blockIdx.x, tid = threadIdx.x;
    for (int i = tid; i < KTAGS * KTAGS; i += 32) sT[i] = trans[i];
    if (tid < KTAGS) sD[tid] = (tid == START_TAG) ? 0.f : NEGV;
    __syncthreads();
    const float* fb = g_feats + (size_t)b * T_ * KTAGS;
    for (int t = 1; t < T_; t++) {
        if (tid < KTAGS) {
            float best = -3.0e38f; int bi = 0;
#pragma unroll
            for (int j = 0; j < KTAGS; j++) {
                float v = sD[j] + sT[tid * KTAGS + j];
                if (v > best) { best = v; bi = j; }
            }
            psi[t - 1][tid] = (unsigned char)bi;
            sDn[tid] = best + fb[t * KTAGS + tid];
        }
        __syncthreads();
        if (tid < KTAGS) sD[tid] = sDn[tid];
        __syncthreads();
    }
    if (tid == 0) {
        float best = -3.0e38f; int last = 0;
        for (int k = 0; k < KTAGS; k++) if (sD[k] > best) { best = sD[k]; last = k; }
        float* so = nullptr; float* po = nullptr;
        if (out_size >= B_ + B_ * T_) { so = out; po = out + B_; }
        else if (out_size >= B_ * T_) { po = out; }
        else { so = out; }
        if (so) so[b] = best;
        if (po) {
            po[(size_t)b * T_ + T_ - 1] = (float)last;
            int cur = last;
            for (int t = T_ - 2; t >= 0; t--) { cur = psi[t][cur]; po[(size_t)b * T_ + t] = (float)cur; }
        }
    }
}

// ================= launcher =================
extern "C" void kernel_launch(void* const* d_in, const int* in_sizes, int n_in,
                              void* d_out, int out_size)
{
    const float* encoded = (const float*)d_in[0];
    const float* w_ih    = (const float*)d_in[1];
    const float* w_hh    = (const float*)d_in[2];
    const float* b_ih    = (const float*)d_in[3];
    const float* b_hh    = (const float*)d_in[4];
    const float* w_out   = (const float*)d_in[5];
    const float* b_out   = (const float*)d_in[6];
    const float* trans   = (const float*)d_in[7];

    cudaFuncSetAttribute(lstm_rec, cudaFuncAttributeMaxDynamicSharedMemorySize, REC_SMEMB);

    dim3 gg(N2 / 128, MTOT / 128);
    for (int layer = 0; layer < 2; layer++) {
        const float* W  = w_ih + (size_t)layer * 2 * G4H * D_;
        const float* bi = b_ih + (size_t)layer * 2 * G4H;
        const float* bh = b_hh + (size_t)layer * 2 * G4H;
        gemm_tf32<<<gg, 256>>>(encoded, W, bi, bh, layer);
        lstm_rec<<<128, 192, REC_SMEMB>>>(w_hh, layer);
    }
    proj_kernel<<<MTOT / 16, 256>>>(w_out, b_out);
    viterbi_kernel<<<B_, 32>>>(trans, (float*)d_out, out_size);
}